// round 1
// baseline (speedup 1.0000x reference)
#include <cuda_runtime.h>

// ---------------------------------------------------------------------------
// BatchedGAT: B=8, N=512, IN=256, H=4, C=32, OUT=128, LeakyReLU slope 0.2
// Kernel 1: projections xl = x@W_l + b_l, xr = x@W_r + b_r  -> [B,H,N,C]
// Kernel 2: per (b,h,i-tile): e_ij = v_j + sum_c 0.4*att_c*|xr_ic + xl_jc|
//           (0.6*att linear part of xr cancels in softmax; xl part = v_j)
//           masked softmax over j, out = (p @ xl) / rowsum + bias
// ---------------------------------------------------------------------------

#define Bn 8
#define Nn 512
#define INDIM 256
#define Hh 4
#define Cc 32
#define ODIM 128

typedef unsigned long long u64;

__device__ float g_xl[Bn * Hh * Nn * Cc];   // [b][h][j][c]
__device__ float g_xr[Bn * Hh * Nn * Cc];   // [b][h][i][c]

__device__ __forceinline__ u64 f2add(u64 a, u64 b) {
    u64 r; asm("add.rn.f32x2 %0, %1, %2;" : "=l"(r) : "l"(a), "l"(b)); return r;
}
__device__ __forceinline__ u64 f2fma(u64 a, u64 b, u64 c) {
    u64 r; asm("fma.rn.f32x2 %0, %1, %2, %3;" : "=l"(r) : "l"(a), "l"(b), "l"(c)); return r;
}
__device__ __forceinline__ float2 f2unpack(u64 v) {
    float2 r; asm("mov.b64 {%0, %1}, %2;" : "=f"(r.x), "=f"(r.y) : "l"(v)); return r;
}

// ---------------------------------------------------------------------------
// Kernel 1: tiled SIMT GEMM. M=4096 (b*n), K=256, Ncols=256 (xl 0..127 | xr 128..255)
// ---------------------------------------------------------------------------
#define BM 64
#define BN 64
#define BK 16

__global__ void __launch_bounds__(256) proj_kernel(
    const float* __restrict__ x,
    const float* __restrict__ Wl, const float* __restrict__ bl,
    const float* __restrict__ Wr, const float* __restrict__ br)
{
    __shared__ float As[BK][BM + 4];
    __shared__ float Bs[BK][BN + 4];

    const int tid = threadIdx.x;
    const int m0 = blockIdx.x * BM;      // 0..4032
    const int n0 = blockIdx.y * BN;      // 0,64,128,192
    const float* W  = (n0 < 128) ? Wl : Wr;
    const float* bb = (n0 < 128) ? bl : br;
    const int wcol0 = n0 & 127;

    const int ty = tid >> 4;             // 0..15
    const int tx = tid & 15;             // 0..15

    // A tile load mapping: one float4 per thread
    const int ar  = tid >> 2;            // 0..63
    const int ak4 = (tid & 3) << 2;      // 0,4,8,12
    // B tile load mapping
    const int bk  = tid >> 4;            // 0..15
    const int bn4 = (tid & 15) << 2;     // 0..60

    float acc[4][4];
    #pragma unroll
    for (int r = 0; r < 4; r++)
        #pragma unroll
        for (int c = 0; c < 4; c++) acc[r][c] = 0.f;

    for (int k0 = 0; k0 < INDIM; k0 += BK) {
        float4 av = *(const float4*)&x[(m0 + ar) * INDIM + k0 + ak4];
        As[ak4 + 0][ar] = av.x;
        As[ak4 + 1][ar] = av.y;
        As[ak4 + 2][ar] = av.z;
        As[ak4 + 3][ar] = av.w;
        float4 bv = *(const float4*)&W[(k0 + bk) * ODIM + wcol0 + bn4];
        *(float4*)&Bs[bk][bn4] = bv;
        __syncthreads();

        #pragma unroll
        for (int kk = 0; kk < BK; kk++) {
            float4 a = *(const float4*)&As[kk][ty * 4];
            float4 b = *(const float4*)&Bs[kk][tx * 4];
            float aa[4] = {a.x, a.y, a.z, a.w};
            float bbv[4] = {b.x, b.y, b.z, b.w};
            #pragma unroll
            for (int r = 0; r < 4; r++)
                #pragma unroll
                for (int c = 0; c < 4; c++) acc[r][c] += aa[r] * bbv[c];
        }
        __syncthreads();
    }

    // epilogue: scatter to g_xl / g_xr as [b][h][n][c]
    #pragma unroll
    for (int r = 0; r < 4; r++) {
        const int m = m0 + ty * 4 + r;     // b*512 + n
        const int bidx = m >> 9;
        const int n = m & 511;
        #pragma unroll
        for (int c = 0; c < 4; c++) {
            const int oc = n0 + tx * 4 + c;   // 0..255
            float v = acc[r][c] + bb[wcol0 + tx * 4 + c];
            const int h = (oc & 127) >> 5;
            const int ch = oc & 31;
            float* dst = (oc < 128) ? g_xl : g_xr;
            dst[(((bidx * Hh + h) * Nn) + n) * Cc + ch] = v;
        }
    }
}

// ---------------------------------------------------------------------------
// Kernel 2: attention. grid (16, 4, 8) = (i-tile, h, b), 256 threads.
// ---------------------------------------------------------------------------
#define XL_STRIDE 36          // padded row stride (floats), conflict-free LDS.128
#define P_STRIDE  516
#define SM_XL     0                         // 512*36   = 18432 floats
#define SM_XR     (SM_XL + Nn * XL_STRIDE)  // 32*32    = 1024
#define SM_P      (SM_XR + 32 * 32)         // 32*516   = 16512
#define SM_V      (SM_P + 32 * P_STRIDE)    // 512
#define SM_W4     (SM_V + Nn)               // 32
#define SM_W6     (SM_W4 + 32)              // 32
#define SM_MASK   (SM_W6 + 32)              // 512 uint32
#define SM_FLOATS (SM_MASK + 512)
#define SMEM_BYTES (SM_FLOATS * 4)          // 148224 bytes

#define ABSMASK 0x7FFFFFFF7FFFFFFFULL
#define NEGINF  __int_as_float(0xff800000)

__global__ void __launch_bounds__(256) gat_kernel(
    const int* __restrict__ adj,
    const float* __restrict__ att,
    const float* __restrict__ bias,
    float* __restrict__ out)
{
    extern __shared__ float sm[];
    float* xl_s = sm + SM_XL;
    float* xr_s = sm + SM_XR;
    float* p_s  = sm + SM_P;
    float* v_s  = sm + SM_V;
    float* w4_s = sm + SM_W4;
    float* w6_s = sm + SM_W6;
    unsigned* mask_s = (unsigned*)(sm + SM_MASK);

    const int tid = threadIdx.x;
    const int b  = blockIdx.z;
    const int h  = blockIdx.y;
    const int i0 = blockIdx.x * 32;

    const float* xl = g_xl + ((b * Hh + h) * Nn) * Cc;
    const float* xr = g_xr + ((b * Hh + h) * Nn + i0) * Cc;

    // ---- Phase A: loads ----
    for (int q = tid; q < Nn * Cc / 4; q += 256) {     // 4096 float4
        int j = q >> 3, cc = (q & 7) << 2;
        float4 v = *(const float4*)&xl[j * Cc + cc];
        *(float4*)&xl_s[j * XL_STRIDE + cc] = v;
    }
    {
        int j = tid >> 3, cc = (tid & 7) << 2;         // 256 float4 = 32x32
        *(float4*)&xr_s[j * Cc + cc] = *(const float4*)&xr[j * Cc + cc];
    }
    if (tid < 32) {
        float a = att[h * Cc + tid];
        w6_s[tid] = 0.6f * a;
        w4_s[tid] = 0.4f * a;
    }
    __syncthreads();

    // v_s[j] = sum_c 0.6*att_c * xl[j][c]
    for (int j = tid; j < Nn; j += 256) {
        float s = 0.f;
        #pragma unroll
        for (int c = 0; c < Cc; c++) s += w6_s[c] * xl_s[j * XL_STRIDE + c];
        v_s[j] = s;
    }

    const int w = tid >> 5;
    const int l = tid & 31;

    // mask bits: mask_s[i][jj] bit l2 = edge (source j=jj*32+l2 -> target i)
    {
        const int* adjb = adj + b * Nn * Nn;
        for (int jj = w; jj < 16; jj += 8) {
            unsigned word = 0;
            #pragma unroll 4
            for (int l2 = 0; l2 < 32; l2++) {
                int j = jj * 32 + l2;
                int av = adjb[j * Nn + i0 + l];
                unsigned pred = (av != 0) || (j == i0 + l);
                word |= pred << l2;
            }
            mask_s[l * 16 + jj] = word;   // row i = l
        }
    }
    __syncthreads();

    // ---- Phase B/C: scores + masked softmax. Warp w owns rows w*4..w*4+3 ----
    u64 w4r[16];
    {
        const ulonglong2* wp = (const ulonglong2*)w4_s;
        #pragma unroll
        for (int k = 0; k < 8; k++) { ulonglong2 t = wp[k]; w4r[2*k] = t.x; w4r[2*k+1] = t.y; }
    }

    float rinv[4];

    #pragma unroll
    for (int ip = 0; ip < 2; ip++) {
        const int ia = w * 4 + ip * 2;      // local row pair (ia, ia+1)
        u64 xra[16], xrb[16];
        {
            const ulonglong2* pa = (const ulonglong2*)&xr_s[ia * Cc];
            const ulonglong2* pb = (const ulonglong2*)&xr_s[(ia + 1) * Cc];
            #pragma unroll
            for (int k = 0; k < 8; k++) {
                ulonglong2 ta = pa[k]; xra[2*k] = ta.x; xra[2*k+1] = ta.y;
                ulonglong2 tb = pb[k]; xrb[2*k] = tb.x; xrb[2*k+1] = tb.y;
            }
        }

        float e0[16], e1[16];
        #pragma unroll
        for (int jj = 0; jj < 16; jj++) {
            const int j = jj * 32 + l;
            const ulonglong2* xv = (const ulonglong2*)&xl_s[j * XL_STRIDE];
            u64 aa0 = 0ull, aa1 = 0ull, bb0 = 0ull, bb1 = 0ull;
            #pragma unroll
            for (int k = 0; k < 8; k++) {
                ulonglong2 q = xv[k];
                u64 sa0 = f2add(xra[2*k],   q.x) & ABSMASK;
                u64 sb0 = f2add(xrb[2*k],   q.x) & ABSMASK;
                u64 sa1 = f2add(xra[2*k+1], q.y) & ABSMASK;
                u64 sb1 = f2add(xrb[2*k+1], q.y) & ABSMASK;
                aa0 = f2fma(w4r[2*k],   sa0, aa0);
                bb0 = f2fma(w4r[2*k],   sb0, bb0);
                aa1 = f2fma(w4r[2*k+1], sa1, aa1);
                bb1 = f2fma(w4r[2*k+1], sb1, bb1);
            }
            float vj = v_s[j];
            float2 fa = f2unpack(f2add(aa0, aa1));
            float2 fb = f2unpack(f2add(bb0, bb1));
            e0[jj] = fa.x + fa.y + vj;
            e1[jj] = fb.x + fb.y + vj;
        }

        // softmax row ia (e0) and row ia+1 (e1)
        #pragma unroll
        for (int rsel = 0; rsel < 2; rsel++) {
            const int irow = ia + rsel;
            float mx = NEGINF;
            #pragma unroll
            for (int jj = 0; jj < 16; jj++) {
                unsigned bw = mask_s[irow * 16 + jj];
                float ev = (rsel == 0) ? e0[jj] : e1[jj];
                float evm = ((bw >> l) & 1u) ? ev : NEGINF;
                mx = fmaxf(mx, evm);
            }
            #pragma unroll
            for (int off = 16; off > 0; off >>= 1)
                mx = fmaxf(mx, __shfl_xor_sync(0xffffffffu, mx, off));

            float sum = 0.f;
            #pragma unroll
            for (int jj = 0; jj < 16; jj++) {
                unsigned bw = mask_s[irow * 16 + jj];
                float ev = (rsel == 0) ? e0[jj] : e1[jj];
                float p = ((bw >> l) & 1u) ? __expf(ev - mx) : 0.f;
                p_s[irow * P_STRIDE + jj * 32 + l] = p;
                sum += p;
            }
            #pragma unroll
            for (int off = 16; off > 0; off >>= 1)
                sum += __shfl_xor_sync(0xffffffffu, sum, off);

            rinv[ip * 2 + rsel] = 1.f / sum;
        }
    }

    __syncwarp();

    // ---- Phase D: out[i][c] = (sum_j p[i][j]*xl[j][c]) * rinv + bias ----
    float oacc[4] = {0.f, 0.f, 0.f, 0.f};
    for (int j4 = 0; j4 < Nn; j4 += 4) {
        float x0 = xl_s[(j4 + 0) * XL_STRIDE + l];
        float x1 = xl_s[(j4 + 1) * XL_STRIDE + l];
        float x2 = xl_s[(j4 + 2) * XL_STRIDE + l];
        float x3 = xl_s[(j4 + 3) * XL_STRIDE + l];
        #pragma unroll
        for (int ii = 0; ii < 4; ii++) {
            float4 p4 = *(const float4*)&p_s[(w * 4 + ii) * P_STRIDE + j4];
            oacc[ii] += p4.x * x0 + p4.y * x1 + p4.z * x2 + p4.w * x3;
        }
    }
    #pragma unroll
    for (int ii = 0; ii < 4; ii++) {
        const int i = i0 + w * 4 + ii;
        out[(b * Nn + i) * ODIM + h * Cc + l] = oacc[ii] * rinv[ii] + bias[h * Cc + l];
    }
}

// ---------------------------------------------------------------------------
extern "C" void kernel_launch(void* const* d_in, const int* in_sizes, int n_in,
                              void* d_out, int out_size)
{
    const float* x    = (const float*)d_in[0];
    const int*   adj  = (const int*)  d_in[1];
    const float* Wl   = (const float*)d_in[2];
    const float* bl   = (const float*)d_in[3];
    const float* Wr   = (const float*)d_in[4];
    const float* br   = (const float*)d_in[5];
    const float* att  = (const float*)d_in[6];
    const float* bias = (const float*)d_in[7];
    float* out = (float*)d_out;

    cudaFuncSetAttribute(gat_kernel, cudaFuncAttributeMaxDynamicSharedMemorySize, SMEM_BYTES);

    dim3 g1(Bn * Nn / BM, (2 * ODIM) / BN);   // (64, 4)
    proj_kernel<<<g1, 256>>>(x, Wl, bl, Wr, br);

    dim3 g2(Nn / 32, Hh, Bn);                 // (16, 4, 8)
    gat_kernel<<<g2, 256, SMEM_BYTES>>>(adj, att, bias, out);
}

// round 2
// speedup vs baseline: 2.1945x; 2.1945x over previous
#include <cuda_runtime.h>

// ---------------------------------------------------------------------------
// BatchedGAT: B=8, N=512, IN=256, H=4, C=32, OUT=128, LeakyReLU slope 0.2
// K1: projections xl = x@W_l + b_l, xr = x@W_r + b_r  -> [B,H,N,C]
// K2: per (b,h,i-tile): e_ij = v_j + sum_c 0.4*att_c*|xr_ic + xl_jc|
//     (0.6*att linear part of xr cancels in softmax; xl part = v_j)
//     masked softmax over j, out = (p @ xl) / rowsum + bias
// ---------------------------------------------------------------------------

#define Bn 8
#define Nn 512
#define INDIM 256
#define Hh 4
#define Cc 32
#define ODIM 128

typedef unsigned long long u64;

__device__ float g_xl[Bn * Hh * Nn * Cc];   // [b][h][j][c]
__device__ float g_xr[Bn * Hh * Nn * Cc];   // [b][h][i][c]

__device__ __forceinline__ u64 f2add(u64 a, u64 b) {
    u64 r; asm("add.rn.f32x2 %0, %1, %2;" : "=l"(r) : "l"(a), "l"(b)); return r;
}
__device__ __forceinline__ u64 f2fma(u64 a, u64 b, u64 c) {
    u64 r; asm("fma.rn.f32x2 %0, %1, %2, %3;" : "=l"(r) : "l"(a), "l"(b), "l"(c)); return r;
}
__device__ __forceinline__ float2 f2unpack(u64 v) {
    float2 r; asm("mov.b64 {%0, %1}, %2;" : "=f"(r.x), "=f"(r.y) : "l"(v)); return r;
}

// ---------------------------------------------------------------------------
// Kernel 1: tiled SIMT GEMM. M=4096 (b*n), K=256, Ncols=256 (xl | xr)
// ---------------------------------------------------------------------------
#define BM 64
#define BN 64
#define BK 16

__global__ void __launch_bounds__(256) proj_kernel(
    const float* __restrict__ x,
    const float* __restrict__ Wl, const float* __restrict__ bl,
    const float* __restrict__ Wr, const float* __restrict__ br)
{
    __shared__ float As[BK][BM + 4];
    __shared__ float Bs[BK][BN + 4];

    const int tid = threadIdx.x;
    const int m0 = blockIdx.x * BM;
    const int n0 = blockIdx.y * BN;
    const float* W  = (n0 < 128) ? Wl : Wr;
    const float* bb = (n0 < 128) ? bl : br;
    const int wcol0 = n0 & 127;

    const int ty = tid >> 4;
    const int tx = tid & 15;
    const int ar  = tid >> 2;
    const int ak4 = (tid & 3) << 2;
    const int bk  = tid >> 4;
    const int bn4 = (tid & 15) << 2;

    float acc[4][4];
    #pragma unroll
    for (int r = 0; r < 4; r++)
        #pragma unroll
        for (int c = 0; c < 4; c++) acc[r][c] = 0.f;

    for (int k0 = 0; k0 < INDIM; k0 += BK) {
        float4 av = *(const float4*)&x[(m0 + ar) * INDIM + k0 + ak4];
        As[ak4 + 0][ar] = av.x;
        As[ak4 + 1][ar] = av.y;
        As[ak4 + 2][ar] = av.z;
        As[ak4 + 3][ar] = av.w;
        float4 bv = *(const float4*)&W[(k0 + bk) * ODIM + wcol0 + bn4];
        *(float4*)&Bs[bk][bn4] = bv;
        __syncthreads();

        #pragma unroll
        for (int kk = 0; kk < BK; kk++) {
            float4 a = *(const float4*)&As[kk][ty * 4];
            float4 b = *(const float4*)&Bs[kk][tx * 4];
            float aa[4] = {a.x, a.y, a.z, a.w};
            float bbv[4] = {b.x, b.y, b.z, b.w};
            #pragma unroll
            for (int r = 0; r < 4; r++)
                #pragma unroll
                for (int c = 0; c < 4; c++) acc[r][c] += aa[r] * bbv[c];
        }
        __syncthreads();
    }

    #pragma unroll
    for (int r = 0; r < 4; r++) {
        const int m = m0 + ty * 4 + r;
        const int bidx = m >> 9;
        const int n = m & 511;
        #pragma unroll
        for (int c = 0; c < 4; c++) {
            const int oc = n0 + tx * 4 + c;
            float v = acc[r][c] + bb[wcol0 + tx * 4 + c];
            const int h = (oc & 127) >> 5;
            const int ch = oc & 31;
            float* dst = (oc < 128) ? g_xl : g_xr;
            dst[(((bidx * Hh + h) * Nn) + n) * Cc + ch] = v;
        }
    }
}

// ---------------------------------------------------------------------------
// Kernel 2: attention. grid (16, 4, 8), 512 threads (16 warps, 2 rows/warp).
// ---------------------------------------------------------------------------
#define XL_STRIDE 36                        // padded row stride, conflict-free
#define SM_XL   0                           // 512*36 = 18432 floats
#define SM_XR   (SM_XL + Nn * XL_STRIDE)    // 32*32  = 1024
#define SM_V    (SM_XR + 32 * 32)           // 512
#define SM_W4   (SM_V + Nn)                 // 32
#define SM_W6   (SM_W4 + 32)                // 32
#define SM_MASK (SM_W6 + 32)                // 512 uint32
#define SM_PB   (SM_MASK + 512)             // 16 warps * 2 slots * 32 float2 = 2048 floats
#define SM_FLOATS (SM_PB + 2048)
#define SMEM_BYTES (SM_FLOATS * 4)          // 90368 bytes

#define ABSMASK 0x7FFFFFFF7FFFFFFFULL
#define NEGINF  __int_as_float(0xff800000)

__global__ void __launch_bounds__(512) gat_kernel(
    const int* __restrict__ adj,
    const float* __restrict__ att,
    const float* __restrict__ bias,
    float* __restrict__ out)
{
    extern __shared__ float sm[];
    float* xl_s = sm + SM_XL;
    float* xr_s = sm + SM_XR;
    float* v_s  = sm + SM_V;
    float* w4_s = sm + SM_W4;
    float* w6_s = sm + SM_W6;
    unsigned* mask_s = (unsigned*)(sm + SM_MASK);
    float2* pb_s = (float2*)(sm + SM_PB);

    const int tid = threadIdx.x;
    const int w = tid >> 5;
    const int l = tid & 31;
    const int b  = blockIdx.z;
    const int h  = blockIdx.y;
    const int i0 = blockIdx.x * 32;

    const float* xl = g_xl + ((b * Hh + h) * Nn) * Cc;
    const float* xr = g_xr + ((b * Hh + h) * Nn + i0) * Cc;

    // ---- mask build: mask_s[j] bit i (local) = edge j -> i0+i ----
    {
        const int* adjb = adj + b * Nn * Nn + i0 + l;
        #pragma unroll 4
        for (int j = w; j < Nn; j += 16) {
            int av = adjb[j * Nn];
            unsigned word = __ballot_sync(0xffffffffu, (av != 0) || (j == i0 + l));
            if (l == 0) mask_s[j] = word;
        }
    }

    // ---- tile loads ----
    for (int q = tid; q < Nn * Cc / 4; q += 512) {
        int j = q >> 3, cc = (q & 7) << 2;
        *(float4*)&xl_s[j * XL_STRIDE + cc] = *(const float4*)&xl[j * Cc + cc];
    }
    if (tid < 256) {
        int j = tid >> 3, cc = (tid & 7) << 2;
        *(float4*)&xr_s[j * Cc + cc] = *(const float4*)&xr[j * Cc + cc];
    }
    if (tid < 32) {
        float a = att[h * Cc + tid];
        w6_s[tid] = 0.6f * a;
        w4_s[tid] = 0.4f * a;
    }
    __syncthreads();

    // v_s[j] = sum_c 0.6*att_c * xl[j][c]
    {
        float s = 0.f;
        #pragma unroll
        for (int c = 0; c < Cc; c++) s += w6_s[c] * xl_s[tid * XL_STRIDE + c];
        v_s[tid] = s;
    }
    __syncthreads();

    // ---- per-warp: rows irow0 = 2w, irow1 = 2w+1 ----
    u64 w4r[16];
    {
        const ulonglong2* wp = (const ulonglong2*)w4_s;
        #pragma unroll
        for (int k = 0; k < 8; k++) { ulonglong2 t = wp[k]; w4r[2*k] = t.x; w4r[2*k+1] = t.y; }
    }

    // mask bits for this lane's 16 j-words, per row
    unsigned mb0 = 0, mb1 = 0;
    #pragma unroll
    for (int jj = 0; jj < 16; jj++) {
        unsigned word = mask_s[jj * 32 + l];
        mb0 |= ((word >> (2 * w)) & 1u) << jj;
        mb1 |= ((word >> (2 * w + 1)) & 1u) << jj;
    }

    float p0[16], p1[16];
    float rinv0, rinv1;

    #pragma unroll
    for (int rs = 0; rs < 2; rs++) {
        const int irow = 2 * w + rs;
        float* ev = rs ? p1 : p0;
        const unsigned mb = rs ? mb1 : mb0;

        u64 xrr[16];
        {
            const ulonglong2* pa = (const ulonglong2*)&xr_s[irow * Cc];
            #pragma unroll
            for (int k = 0; k < 8; k++) { ulonglong2 t = pa[k]; xrr[2*k] = t.x; xrr[2*k+1] = t.y; }
        }

        #pragma unroll
        for (int jj = 0; jj < 16; jj++) {
            const int j = jj * 32 + l;
            const ulonglong2* xv = (const ulonglong2*)&xl_s[j * XL_STRIDE];
            u64 a0 = 0ull, a1 = 0ull;
            #pragma unroll
            for (int k = 0; k < 8; k++) {
                ulonglong2 q = xv[k];
                u64 s0 = f2add(xrr[2*k],   q.x) & ABSMASK;
                u64 s1 = f2add(xrr[2*k+1], q.y) & ABSMASK;
                a0 = f2fma(w4r[2*k],   s0, a0);
                a1 = f2fma(w4r[2*k+1], s1, a1);
            }
            float2 f = f2unpack(f2add(a0, a1));
            ev[jj] = f.x + f.y + v_s[j];
        }

        // masked softmax over j
        float mx = NEGINF;
        #pragma unroll
        for (int jj = 0; jj < 16; jj++) {
            float evm = ((mb >> jj) & 1u) ? ev[jj] : NEGINF;
            mx = fmaxf(mx, evm);
        }
        #pragma unroll
        for (int off = 16; off > 0; off >>= 1)
            mx = fmaxf(mx, __shfl_xor_sync(0xffffffffu, mx, off));

        float sum = 0.f;
        #pragma unroll
        for (int jj = 0; jj < 16; jj++) {
            float p = ((mb >> jj) & 1u) ? __expf(ev[jj] - mx) : 0.f;
            ev[jj] = p;
            sum += p;
        }
        #pragma unroll
        for (int off = 16; off > 0; off >>= 1)
            sum += __shfl_xor_sync(0xffffffffu, sum, off);

        if (rs == 0) rinv0 = 1.f / sum; else rinv1 = 1.f / sum;
    }

    // ---- Phase D: out[irow][c] = (sum_j p[irow][j]*xl[j][c]) * rinv + bias
    // transpose p through per-warp double-buffered 32-entry float2 buffer
    float oacc0 = 0.f, oacc1 = 0.f;
    float2* pb = pb_s + w * 64;          // 2 slots * 32
    #pragma unroll
    for (int jj = 0; jj < 16; jj++) {
        float2* slot = pb + (jj & 1) * 32;
        slot[l] = make_float2(p0[jj], p1[jj]);
        __syncwarp();
        #pragma unroll
        for (int l2 = 0; l2 < 32; l2++) {
            float2 pv = slot[l2];
            float xv = xl_s[(jj * 32 + l2) * XL_STRIDE + l];
            oacc0 += pv.x * xv;
            oacc1 += pv.y * xv;
        }
    }

    const float bv = bias[h * Cc + l];
    {
        const int i = i0 + 2 * w;
        out[(b * Nn + i) * ODIM + h * Cc + l]       = oacc0 * rinv0 + bv;
        out[(b * Nn + i + 1) * ODIM + h * Cc + l]   = oacc1 * rinv1 + bv;
    }
}

// ---------------------------------------------------------------------------
extern "C" void kernel_launch(void* const* d_in, const int* in_sizes, int n_in,
                              void* d_out, int out_size)
{
    const float* x    = (const float*)d_in[0];
    const int*   adj  = (const int*)  d_in[1];
    const float* Wl   = (const float*)d_in[2];
    const float* bl   = (const float*)d_in[3];
    const float* Wr   = (const float*)d_in[4];
    const float* br   = (const float*)d_in[5];
    const float* att  = (const float*)d_in[6];
    const float* bias = (const float*)d_in[7];
    float* out = (float*)d_out;

    cudaFuncSetAttribute(gat_kernel, cudaFuncAttributeMaxDynamicSharedMemorySize, SMEM_BYTES);

    dim3 g1(Bn * Nn / BM, (2 * ODIM) / BN);   // (64, 4)
    proj_kernel<<<g1, 256>>>(x, Wl, bl, Wr, br);

    dim3 g2(Nn / 32, Hh, Bn);                 // (16, 4, 8)
    gat_kernel<<<g2, 512, SMEM_BYTES>>>(adj, att, bias, out);
}

// round 4
// speedup vs baseline: 3.1409x; 1.4313x over previous
#include <cuda_runtime.h>

// ---------------------------------------------------------------------------
// BatchedGAT: B=8, N=512, IN=256, H=4, C=32, OUT=128, LeakyReLU slope 0.2
// K0: mask precompute (head-invariant): bit-packed adjacency^T + forced diag
// K1: projections xl = x@W_l + b_l, xr = x@W_r + b_r  -> [B,H,N,C]
// K2: e_ij = v_j + sum_c 0.4*att_c*|xr_ic + xl_jc|  (linear xr part cancels
//     in softmax; xl part = v_j), masked softmax, out = (p@xl)/rowsum + bias
// ---------------------------------------------------------------------------

#define Bn 8
#define Nn 512
#define INDIM 256
#define Hh 4
#define Cc 32
#define ODIM 128

typedef unsigned long long u64;

__device__ float g_xl[Bn * Hh * Nn * Cc];        // [b][h][j][c]
__device__ float g_xr[Bn * Hh * Nn * Cc];        // [b][h][i][c]
__device__ unsigned g_mask[Bn * 16 * Nn];        // [b][iw][j], bit i(local)

__device__ __forceinline__ u64 f2add(u64 a, u64 b) {
    u64 r; asm("add.rn.f32x2 %0, %1, %2;" : "=l"(r) : "l"(a), "l"(b)); return r;
}
__device__ __forceinline__ u64 f2fma(u64 a, u64 b, u64 c) {
    u64 r; asm("fma.rn.f32x2 %0, %1, %2, %3;" : "=l"(r) : "l"(a), "l"(b), "l"(c)); return r;
}
__device__ __forceinline__ float2 f2unpack(u64 v) {
    float2 r; asm("mov.b64 {%0, %1}, %2;" : "=f"(r.x), "=f"(r.y) : "l"(v)); return r;
}

#define ABSMASK 0x7FFFFFFF7FFFFFFFULL
#define NEGINF  __int_as_float(0xff800000)

// ---------------------------------------------------------------------------
// Kernel 0: mask precompute. grid (8, 16), block 256.
// ---------------------------------------------------------------------------
__global__ void __launch_bounds__(256) mask_kernel(const int* __restrict__ adj)
{
    const int b = blockIdx.x, iw = blockIdx.y;
    const int w = threadIdx.x >> 5, l = threadIdx.x & 31;
    const int ig = iw * 32 + l;
    const int* a = adj + b * Nn * Nn + iw * 32 + l;
    unsigned* dst = g_mask + (b * 16 + iw) * Nn;
    const int j0 = w * 64;
    #pragma unroll 4
    for (int j = j0; j < j0 + 64; j++) {
        int av = a[j * Nn];
        unsigned word = __ballot_sync(0xffffffffu, (av != 0) || (j == ig));
        if (l == 0) dst[j] = word;
    }
}

// ---------------------------------------------------------------------------
// Kernel 1: tiled SIMT GEMM. M=4096 (b*n), K=256, Ncols=256 (xl | xr)
// ---------------------------------------------------------------------------
#define BM 64
#define BN 64
#define BK 16

__global__ void __launch_bounds__(256) proj_kernel(
    const float* __restrict__ x,
    const float* __restrict__ Wl, const float* __restrict__ bl,
    const float* __restrict__ Wr, const float* __restrict__ br)
{
    __shared__ float As[BK][BM + 4];
    __shared__ float Bs[BK][BN + 4];

    const int tid = threadIdx.x;
    const int m0 = blockIdx.x * BM;
    const int n0 = blockIdx.y * BN;
    const float* W  = (n0 < 128) ? Wl : Wr;
    const float* bb = (n0 < 128) ? bl : br;
    const int wcol0 = n0 & 127;

    const int ty = tid >> 4;
    const int tx = tid & 15;
    const int ar  = tid >> 2;
    const int ak4 = (tid & 3) << 2;
    const int bk  = tid >> 4;
    const int bn4 = (tid & 15) << 2;

    float acc[4][4];
    #pragma unroll
    for (int r = 0; r < 4; r++)
        #pragma unroll
        for (int c = 0; c < 4; c++) acc[r][c] = 0.f;

    for (int k0 = 0; k0 < INDIM; k0 += BK) {
        float4 av = *(const float4*)&x[(m0 + ar) * INDIM + k0 + ak4];
        As[ak4 + 0][ar] = av.x;
        As[ak4 + 1][ar] = av.y;
        As[ak4 + 2][ar] = av.z;
        As[ak4 + 3][ar] = av.w;
        float4 bv = *(const float4*)&W[(k0 + bk) * ODIM + wcol0 + bn4];
        *(float4*)&Bs[bk][bn4] = bv;
        __syncthreads();

        #pragma unroll
        for (int kk = 0; kk < BK; kk++) {
            float4 a = *(const float4*)&As[kk][ty * 4];
            float4 b = *(const float4*)&Bs[kk][tx * 4];
            float aa[4] = {a.x, a.y, a.z, a.w};
            float bbv[4] = {b.x, b.y, b.z, b.w};
            #pragma unroll
            for (int r = 0; r < 4; r++)
                #pragma unroll
                for (int c = 0; c < 4; c++) acc[r][c] += aa[r] * bbv[c];
        }
        __syncthreads();
    }

    #pragma unroll
    for (int r = 0; r < 4; r++) {
        const int m = m0 + ty * 4 + r;
        const int bidx = m >> 9;
        const int n = m & 511;
        #pragma unroll
        for (int c = 0; c < 4; c++) {
            const int oc = n0 + tx * 4 + c;
            float v = acc[r][c] + bb[wcol0 + tx * 4 + c];
            const int h = (oc & 127) >> 5;
            const int ch = oc & 31;
            float* dst = (oc < 128) ? g_xl : g_xr;
            dst[(((bidx * Hh + h) * Nn) + n) * Cc + ch] = v;
        }
    }
}

// ---------------------------------------------------------------------------
// Kernel 2: attention. grid (16, 4, 8), 512 threads.
// ---------------------------------------------------------------------------
#define XL_ST 36
#define ES_ST 516
#define SM_XL   0                          // 512*36 = 18432
#define SM_XR   (SM_XL + Nn * XL_ST)       // 1024
#define SM_ES   (SM_XR + 1024)             // 32*516 = 16512
#define SM_MASK (SM_ES + 32 * ES_ST)       // 512
#define SM_W4   (SM_MASK + 512)            // 32
#define SM_W6   (SM_W4 + 32)               // 32
#define SM_RINV (SM_W6 + 32)               // 32
#define SM_PS   (SM_RINV + 32)             // 2 halves * 32 rows * 32 ch = 2048
#define SM_FLOATS (SM_PS + 2048)
#define SMEM_BYTES (SM_FLOATS * 4)         // 154496 bytes

__global__ void __launch_bounds__(512) gat_kernel(
    const float* __restrict__ att,
    const float* __restrict__ bias,
    float* __restrict__ out)
{
    extern __shared__ float sm[];
    float* xl_s = sm + SM_XL;
    float* xr_s = sm + SM_XR;
    float* e_s  = sm + SM_ES;
    unsigned* mask_s = (unsigned*)(sm + SM_MASK);
    float* w4_s = sm + SM_W4;
    float* w6_s = sm + SM_W6;
    float* rinv_s = sm + SM_RINV;
    float* ps_s = sm + SM_PS;

    const int tid = threadIdx.x;
    const int w = tid >> 5;
    const int l = tid & 31;
    const int b  = blockIdx.z;
    const int h  = blockIdx.y;
    const int bx = blockIdx.x;
    const int i0 = bx * 32;

    const float* xl = g_xl + ((b * Hh + h) * Nn) * Cc;
    const float* xr = g_xr + ((b * Hh + h) * Nn + i0) * Cc;

    // ---- loads ----
    #pragma unroll
    for (int q8 = 0; q8 < 8; q8++) {
        int idx = q8 * 512 + tid;          // 4096 float4
        int j = idx >> 3, cc = (idx & 7) << 2;
        *(float4*)&xl_s[j * XL_ST + cc] = *(const float4*)&xl[j * Cc + cc];
    }
    if (tid < 256) {
        int j = tid >> 3, cc = (tid & 7) << 2;
        *(float4*)&xr_s[j * Cc + cc] = *(const float4*)&xr[j * Cc + cc];
    }
    mask_s[tid] = g_mask[(b * 16 + bx) * Nn + tid];
    if (tid < 32) {
        float a = att[h * Cc + tid];
        w4_s[tid] = 0.4f * a;
        w6_s[tid] = 0.6f * a;
    }
    __syncthreads();

    // ---- Phase 1: e scores, j-sliced. Warp w owns j = 32w + l ----
    {
        const int j = w * 32 + l;
        u64 q[16];
        {
            const ulonglong2* qp = (const ulonglong2*)&xl_s[j * XL_ST];
            #pragma unroll
            for (int k = 0; k < 8; k++) { ulonglong2 t = qp[k]; q[2*k] = t.x; q[2*k+1] = t.y; }
        }
        u64 w4r[16];
        {
            const ulonglong2* wp = (const ulonglong2*)w4_s;
            #pragma unroll
            for (int k = 0; k < 8; k++) { ulonglong2 t = wp[k]; w4r[2*k] = t.x; w4r[2*k+1] = t.y; }
        }
        float v;
        {
            const u64* w6p = (const u64*)w6_s;
            u64 va = 0ull, vb = 0ull;
            #pragma unroll
            for (int k = 0; k < 16; k += 2) {
                va = f2fma(w6p[k],   q[k],   va);
                vb = f2fma(w6p[k+1], q[k+1], vb);
            }
            float2 f = f2unpack(f2add(va, vb));
            v = f.x + f.y;
        }
        const unsigned m = mask_s[j];
        float* erow = &e_s[w * 32 + l];

        #pragma unroll 4
        for (int i = 0; i < 32; i++) {
            const ulonglong2* xp = (const ulonglong2*)&xr_s[i * Cc];
            u64 a0 = 0ull, a1 = 0ull, a2 = 0ull, a3 = 0ull;
            #pragma unroll
            for (int k = 0; k < 8; k += 2) {
                ulonglong2 t0 = xp[k], t1 = xp[k+1];
                u64 s0 = f2add(t0.x, q[2*k])   & ABSMASK;
                u64 s1 = f2add(t0.y, q[2*k+1]) & ABSMASK;
                u64 s2 = f2add(t1.x, q[2*k+2]) & ABSMASK;
                u64 s3 = f2add(t1.y, q[2*k+3]) & ABSMASK;
                a0 = f2fma(w4r[2*k],   s0, a0);
                a1 = f2fma(w4r[2*k+1], s1, a1);
                a2 = f2fma(w4r[2*k+2], s2, a2);
                a3 = f2fma(w4r[2*k+3], s3, a3);
            }
            float2 f = f2unpack(f2add(f2add(a0, a1), f2add(a2, a3)));
            float e = f.x + f.y + v;
            e = ((m >> i) & 1u) ? e : NEGINF;
            erow[i * ES_ST] = e;
        }
    }
    __syncthreads();

    // ---- Phase 2: masked softmax. Warp w owns rows 2w, 2w+1 ----
    #pragma unroll
    for (int rs = 0; rs < 2; rs++) {
        const int r = 2 * w + rs;
        float vals[16];
        #pragma unroll
        for (int p4 = 0; p4 < 4; p4++) {
            float4 f = *(float4*)&e_s[r * ES_ST + p4 * 128 + l * 4];
            vals[p4*4]   = f.x; vals[p4*4+1] = f.y;
            vals[p4*4+2] = f.z; vals[p4*4+3] = f.w;
        }
        float mx = vals[0];
        #pragma unroll
        for (int k = 1; k < 16; k++) mx = fmaxf(mx, vals[k]);
        #pragma unroll
        for (int off = 16; off > 0; off >>= 1)
            mx = fmaxf(mx, __shfl_xor_sync(0xffffffffu, mx, off));
        float sum = 0.f;
        #pragma unroll
        for (int k = 0; k < 16; k++) {
            float p = __expf(vals[k] - mx);
            vals[k] = p;
            sum += p;
        }
        #pragma unroll
        for (int off = 16; off > 0; off >>= 1)
            sum += __shfl_xor_sync(0xffffffffu, sum, off);
        #pragma unroll
        for (int p4 = 0; p4 < 4; p4++) {
            *(float4*)&e_s[r * ES_ST + p4 * 128 + l * 4] =
                make_float4(vals[p4*4], vals[p4*4+1], vals[p4*4+2], vals[p4*4+3]);
        }
        if (l == 0) rinv_s[r] = 1.f / sum;
    }
    __syncthreads();

    // ---- Phase D: warp w -> rows 4*(w&7)..+3, j-half (w>>3)*256 ----
    {
        const int rbase = 4 * (w & 7);
        const int half = w >> 3;
        const int J0 = half * 256;
        const int jp = l >> 3, cq = l & 7;
        float acc[4][4];
        #pragma unroll
        for (int rr = 0; rr < 4; rr++)
            #pragma unroll
            for (int k = 0; k < 4; k++) acc[rr][k] = 0.f;

        #pragma unroll 2
        for (int jjc = 0; jjc < 8; jjc++) {
            const int jbase = J0 + jjc * 32 + jp;
            #pragma unroll
            for (int g = 0; g < 8; g++) {
                const int jrow = jbase + g * 4;
                float4 xv = *(const float4*)&xl_s[jrow * XL_ST + cq * 4];
                #pragma unroll
                for (int rr = 0; rr < 4; rr++) {
                    float p = e_s[(rbase + rr) * ES_ST + jrow];
                    acc[rr][0] += p * xv.x;
                    acc[rr][1] += p * xv.y;
                    acc[rr][2] += p * xv.z;
                    acc[rr][3] += p * xv.w;
                }
            }
        }
        // reduce over jp (bits 3,4 of lane id)
        #pragma unroll
        for (int off = 8; off <= 16; off <<= 1)
            #pragma unroll
            for (int rr = 0; rr < 4; rr++)
                #pragma unroll
                for (int k = 0; k < 4; k++)
                    acc[rr][k] += __shfl_xor_sync(0xffffffffu, acc[rr][k], off);

        if (l < 8) {
            #pragma unroll
            for (int rr = 0; rr < 4; rr++)
                *(float4*)&ps_s[half * 1024 + (rbase + rr) * 32 + cq * 4] =
                    make_float4(acc[rr][0], acc[rr][1], acc[rr][2], acc[rr][3]);
        }
    }
    __syncthreads();

    // ---- combine halves + scale + bias + store: warp w rows 2w, 2w+1 ----
    {
        const float bv = bias[h * Cc + l];
        #pragma unroll
        for (int rs = 0; rs < 2; rs++) {
            const int r = 2 * w + rs;
            float val = ps_s[r * 32 + l] + ps_s[1024 + r * 32 + l];
            out[(b * Nn + i0 + r) * ODIM + h * Cc + l] = val * rinv_s[r] + bv;
        }
    }
}

// ---------------------------------------------------------------------------
extern "C" void kernel_launch(void* const* d_in, const int* in_sizes, int n_in,
                              void* d_out, int out_size)
{
    const float* x    = (const float*)d_in[0];
    const int*   adj  = (const int*)  d_in[1];
    const float* Wl   = (const float*)d_in[2];
    const float* bl   = (const float*)d_in[3];
    const float* Wr   = (const float*)d_in[4];
    const float* br   = (const float*)d_in[5];
    const float* att  = (const float*)d_in[6];
    const float* bias = (const float*)d_in[7];
    float* out = (float*)d_out;

    cudaFuncSetAttribute(gat_kernel, cudaFuncAttributeMaxDynamicSharedMemorySize, SMEM_BYTES);

    dim3 g0(Bn, 16);
    mask_kernel<<<g0, 256>>>(adj);

    dim3 g1(Bn * Nn / BM, (2 * ODIM) / BN);   // (64, 4)
    proj_kernel<<<g1, 256>>>(x, Wl, bl, Wr, br);

    dim3 g2(Nn / 32, Hh, Bn);                 // (16, 4, 8)
    gat_kernel<<<g2, 512, SMEM_BYTES>>>(att, bias, out);
}

// round 5
// speedup vs baseline: 3.1713x; 1.0097x over previous
#include <cuda_runtime.h>

// ---------------------------------------------------------------------------
// BatchedGAT: B=8, N=512, IN=256, H=4, C=32, OUT=128, LeakyReLU slope 0.2
// K0: mask precompute (head-invariant): bit-packed adjacency^T + forced diag
// K1: projections xl = x@W_l + b_l, xr = x@W_r + b_r  -> [B,H,N,C]  (f32x2)
// K2: e_ij = v_j + sum_c 0.4*att_c*|xr_ic + xl_jc|  (linear xr part cancels
//     in softmax; xl part = v_j), masked softmax, out = (p@xl)/rowsum + bias
// ---------------------------------------------------------------------------

#define Bn 8
#define Nn 512
#define INDIM 256
#define Hh 4
#define Cc 32
#define ODIM 128

typedef unsigned long long u64;

__device__ float g_xl[Bn * Hh * Nn * Cc];        // [b][h][j][c]
__device__ float g_xr[Bn * Hh * Nn * Cc];        // [b][h][i][c]
__device__ unsigned g_mask[Bn * 16 * Nn];        // [b][iw][j], bit i(local)

__device__ __forceinline__ u64 f2add(u64 a, u64 b) {
    u64 r; asm("add.rn.f32x2 %0, %1, %2;" : "=l"(r) : "l"(a), "l"(b)); return r;
}
__device__ __forceinline__ u64 f2fma(u64 a, u64 b, u64 c) {
    u64 r; asm("fma.rn.f32x2 %0, %1, %2, %3;" : "=l"(r) : "l"(a), "l"(b), "l"(c)); return r;
}
__device__ __forceinline__ float2 f2unpack(u64 v) {
    float2 r; asm("mov.b64 {%0, %1}, %2;" : "=f"(r.x), "=f"(r.y) : "l"(v)); return r;
}
__device__ __forceinline__ u64 f2dup(float p) {
    u64 r; asm("mov.b64 %0, {%1, %1};" : "=l"(r) : "f"(p)); return r;
}

#define ABSMASK 0x7FFFFFFF7FFFFFFFULL
#define NEGINF  __int_as_float(0xff800000)

// ---------------------------------------------------------------------------
// Kernel 0: mask precompute. grid (8, 16, 8), block 256; warp owns 8 j's.
// ---------------------------------------------------------------------------
__global__ void __launch_bounds__(256) mask_kernel(const int* __restrict__ adj)
{
    const int b = blockIdx.x, iw = blockIdx.y, jc = blockIdx.z;
    const int w = threadIdx.x >> 5, l = threadIdx.x & 31;
    const int ig = iw * 32 + l;
    const int* a = adj + b * Nn * Nn + iw * 32 + l;
    unsigned* dst = g_mask + (b * 16 + iw) * Nn;
    const int j0 = jc * 64 + w * 8;

    int av[8];
    #pragma unroll
    for (int k = 0; k < 8; k++) av[k] = a[(j0 + k) * Nn];   // MLP 8
    #pragma unroll
    for (int k = 0; k < 8; k++) {
        const int j = j0 + k;
        unsigned word = __ballot_sync(0xffffffffu, (av[k] != 0) || (j == ig));
        if (l == 0) dst[j] = word;
    }
}

// ---------------------------------------------------------------------------
// Kernel 1: tiled SIMT GEMM (f32x2). M=4096, K=256, Ncols=256 (xl | xr)
// ---------------------------------------------------------------------------
#define BM 64
#define BN 64
#define BK 16

__global__ void __launch_bounds__(256) proj_kernel(
    const float* __restrict__ x,
    const float* __restrict__ Wl, const float* __restrict__ bl,
    const float* __restrict__ Wr, const float* __restrict__ br)
{
    __shared__ float As[BK][BM + 4];
    __shared__ float Bs[BK][BN + 4];

    const int tid = threadIdx.x;
    const int m0 = blockIdx.x * BM;
    const int n0 = blockIdx.y * BN;
    const float* W  = (n0 < 128) ? Wl : Wr;
    const float* bb = (n0 < 128) ? bl : br;
    const int wcol0 = n0 & 127;

    const int ty = tid >> 4;
    const int tx = tid & 15;
    const int ar  = tid >> 2;
    const int ak4 = (tid & 3) << 2;
    const int bk  = tid >> 4;
    const int bn4 = (tid & 15) << 2;

    u64 acc[4][2];
    #pragma unroll
    for (int r = 0; r < 4; r++) { acc[r][0] = 0ull; acc[r][1] = 0ull; }

    for (int k0 = 0; k0 < INDIM; k0 += BK) {
        float4 av = *(const float4*)&x[(m0 + ar) * INDIM + k0 + ak4];
        As[ak4 + 0][ar] = av.x;
        As[ak4 + 1][ar] = av.y;
        As[ak4 + 2][ar] = av.z;
        As[ak4 + 3][ar] = av.w;
        float4 bv = *(const float4*)&W[(k0 + bk) * ODIM + wcol0 + bn4];
        *(float4*)&Bs[bk][bn4] = bv;
        __syncthreads();

        #pragma unroll
        for (int kk = 0; kk < BK; kk++) {
            ulonglong2 b2 = *(const ulonglong2*)&Bs[kk][tx * 4];
            float4 a = *(const float4*)&As[kk][ty * 4];
            u64 a0 = f2dup(a.x), a1 = f2dup(a.y), a2 = f2dup(a.z), a3 = f2dup(a.w);
            acc[0][0] = f2fma(a0, b2.x, acc[0][0]);
            acc[0][1] = f2fma(a0, b2.y, acc[0][1]);
            acc[1][0] = f2fma(a1, b2.x, acc[1][0]);
            acc[1][1] = f2fma(a1, b2.y, acc[1][1]);
            acc[2][0] = f2fma(a2, b2.x, acc[2][0]);
            acc[2][1] = f2fma(a2, b2.y, acc[2][1]);
            acc[3][0] = f2fma(a3, b2.x, acc[3][0]);
            acc[3][1] = f2fma(a3, b2.y, acc[3][1]);
        }
        __syncthreads();
    }

    #pragma unroll
    for (int r = 0; r < 4; r++) {
        const int m = m0 + ty * 4 + r;
        const int bidx = m >> 9;
        const int n = m & 511;
        float2 lo = f2unpack(acc[r][0]);
        float2 hi = f2unpack(acc[r][1]);
        float vr[4] = {lo.x, lo.y, hi.x, hi.y};
        #pragma unroll
        for (int c = 0; c < 4; c++) {
            const int oc = n0 + tx * 4 + c;
            float v = vr[c] + bb[wcol0 + tx * 4 + c];
            const int h = (oc & 127) >> 5;
            const int ch = oc & 31;
            float* dst = (oc < 128) ? g_xl : g_xr;
            dst[(((bidx * Hh + h) * Nn) + n) * Cc + ch] = v;
        }
    }
}

// ---------------------------------------------------------------------------
// Kernel 2: attention. grid (16, 4, 8), 512 threads.
// ---------------------------------------------------------------------------
#define XL_ST 36
#define ES_ST 516
#define SM_XL   0                          // 512*36 = 18432
#define SM_XR   (SM_XL + Nn * XL_ST)       // 1024
#define SM_ES   (SM_XR + 1024)             // 32*516 = 16512
#define SM_MASK (SM_ES + 32 * ES_ST)       // 512
#define SM_W4   (SM_MASK + 512)            // 32
#define SM_W6   (SM_W4 + 32)               // 32
#define SM_RINV (SM_W6 + 32)               // 32
#define SM_PS   (SM_RINV + 32)             // 2 halves * 32 rows * 32 ch = 2048
#define SM_FLOATS (SM_PS + 2048)
#define SMEM_BYTES (SM_FLOATS * 4)         // ~154.5 KB

__global__ void __launch_bounds__(512) gat_kernel(
    const float* __restrict__ att,
    const float* __restrict__ bias,
    float* __restrict__ out)
{
    extern __shared__ float sm[];
    float* xl_s = sm + SM_XL;
    float* xr_s = sm + SM_XR;
    float* e_s  = sm + SM_ES;
    unsigned* mask_s = (unsigned*)(sm + SM_MASK);
    float* w4_s = sm + SM_W4;
    float* w6_s = sm + SM_W6;
    float* rinv_s = sm + SM_RINV;
    float* ps_s = sm + SM_PS;

    const int tid = threadIdx.x;
    const int w = tid >> 5;
    const int l = tid & 31;
    const int b  = blockIdx.z;
    const int h  = blockIdx.y;
    const int bx = blockIdx.x;
    const int i0 = bx * 32;

    const float* xl = g_xl + ((b * Hh + h) * Nn) * Cc;
    const float* xr = g_xr + ((b * Hh + h) * Nn + i0) * Cc;

    // ---- loads ----
    #pragma unroll
    for (int q8 = 0; q8 < 8; q8++) {
        int idx = q8 * 512 + tid;          // 4096 float4
        int j = idx >> 3, cc = (idx & 7) << 2;
        *(float4*)&xl_s[j * XL_ST + cc] = *(const float4*)&xl[j * Cc + cc];
    }
    if (tid < 256) {
        int j = tid >> 3, cc = (tid & 7) << 2;
        *(float4*)&xr_s[j * Cc + cc] = *(const float4*)&xr[j * Cc + cc];
    }
    mask_s[tid] = g_mask[(b * 16 + bx) * Nn + tid];
    if (tid < 32) {
        float a = att[h * Cc + tid];
        w4_s[tid] = 0.4f * a;
        w6_s[tid] = 0.6f * a;
    }
    __syncthreads();

    // ---- Phase 1: e scores, j-sliced. Warp w owns j = 32w + l ----
    {
        const int j = w * 32 + l;
        u64 q[16];
        {
            const ulonglong2* qp = (const ulonglong2*)&xl_s[j * XL_ST];
            #pragma unroll
            for (int k = 0; k < 8; k++) { ulonglong2 t = qp[k]; q[2*k] = t.x; q[2*k+1] = t.y; }
        }
        u64 w4r[16];
        {
            const ulonglong2* wp = (const ulonglong2*)w4_s;
            #pragma unroll
            for (int k = 0; k < 8; k++) { ulonglong2 t = wp[k]; w4r[2*k] = t.x; w4r[2*k+1] = t.y; }
        }
        float v;
        {
            const u64* w6p = (const u64*)w6_s;
            u64 va = 0ull, vb = 0ull;
            #pragma unroll
            for (int k = 0; k < 16; k += 2) {
                va = f2fma(w6p[k],   q[k],   va);
                vb = f2fma(w6p[k+1], q[k+1], vb);
            }
            float2 f = f2unpack(f2add(va, vb));
            v = f.x + f.y;
        }
        const unsigned m = mask_s[j];
        float* erow = &e_s[w * 32 + l];

        #pragma unroll 4
        for (int i = 0; i < 32; i++) {
            const ulonglong2* xp = (const ulonglong2*)&xr_s[i * Cc];
            u64 a0 = 0ull, a1 = 0ull, a2 = 0ull, a3 = 0ull;
            #pragma unroll
            for (int k = 0; k < 8; k += 2) {
                ulonglong2 t0 = xp[k], t1 = xp[k+1];
                u64 s0 = f2add(t0.x, q[2*k])   & ABSMASK;
                u64 s1 = f2add(t0.y, q[2*k+1]) & ABSMASK;
                u64 s2 = f2add(t1.x, q[2*k+2]) & ABSMASK;
                u64 s3 = f2add(t1.y, q[2*k+3]) & ABSMASK;
                a0 = f2fma(w4r[2*k],   s0, a0);
                a1 = f2fma(w4r[2*k+1], s1, a1);
                a2 = f2fma(w4r[2*k+2], s2, a2);
                a3 = f2fma(w4r[2*k+3], s3, a3);
            }
            float2 f = f2unpack(f2add(f2add(a0, a1), f2add(a2, a3)));
            float e = f.x + f.y + v;
            e = ((m >> i) & 1u) ? e : NEGINF;
            erow[i * ES_ST] = e;
        }
    }
    __syncthreads();

    // ---- Phase 2: masked softmax. Warp w owns rows 2w, 2w+1 ----
    #pragma unroll
    for (int rs = 0; rs < 2; rs++) {
        const int r = 2 * w + rs;
        float vals[16];
        #pragma unroll
        for (int p4 = 0; p4 < 4; p4++) {
            float4 f = *(float4*)&e_s[r * ES_ST + p4 * 128 + l * 4];
            vals[p4*4]   = f.x; vals[p4*4+1] = f.y;
            vals[p4*4+2] = f.z; vals[p4*4+3] = f.w;
        }
        float mx = vals[0];
        #pragma unroll
        for (int k = 1; k < 16; k++) mx = fmaxf(mx, vals[k]);
        #pragma unroll
        for (int off = 16; off > 0; off >>= 1)
            mx = fmaxf(mx, __shfl_xor_sync(0xffffffffu, mx, off));
        float sum = 0.f;
        #pragma unroll
        for (int k = 0; k < 16; k++) {
            float p = __expf(vals[k] - mx);
            vals[k] = p;
            sum += p;
        }
        #pragma unroll
        for (int off = 16; off > 0; off >>= 1)
            sum += __shfl_xor_sync(0xffffffffu, sum, off);
        #pragma unroll
        for (int p4 = 0; p4 < 4; p4++) {
            *(float4*)&e_s[r * ES_ST + p4 * 128 + l * 4] =
                make_float4(vals[p4*4], vals[p4*4+1], vals[p4*4+2], vals[p4*4+3]);
        }
        if (l == 0) rinv_s[r] = 1.f / sum;
    }
    __syncthreads();

    // ---- Phase D (f32x2): warp w -> rows 4*(w&7)..+3, j-half (w>>3)*256 ----
    {
        const int rbase = 4 * (w & 7);
        const int half = w >> 3;
        const int J0 = half * 256;
        const int jp = l >> 3, cq = l & 7;
        u64 acc[4][2];
        #pragma unroll
        for (int rr = 0; rr < 4; rr++) { acc[rr][0] = 0ull; acc[rr][1] = 0ull; }

        #pragma unroll 2
        for (int jjc = 0; jjc < 8; jjc++) {
            const int jbase = J0 + jjc * 32 + jp;
            #pragma unroll
            for (int g = 0; g < 8; g++) {
                const int jrow = jbase + g * 4;
                ulonglong2 xv = *(const ulonglong2*)&xl_s[jrow * XL_ST + cq * 4];
                #pragma unroll
                for (int rr = 0; rr < 4; rr++) {
                    u64 pp = f2dup(e_s[(rbase + rr) * ES_ST + jrow]);
                    acc[rr][0] = f2fma(pp, xv.x, acc[rr][0]);
                    acc[rr][1] = f2fma(pp, xv.y, acc[rr][1]);
                }
            }
        }
        // unpack and reduce over jp (lane bits 3,4)
        #pragma unroll
        for (int rr = 0; rr < 4; rr++) {
            float2 lo = f2unpack(acc[rr][0]);
            float2 hi = f2unpack(acc[rr][1]);
            float v0 = lo.x, v1 = lo.y, v2 = hi.x, v3 = hi.y;
            #pragma unroll
            for (int off = 8; off <= 16; off <<= 1) {
                v0 += __shfl_xor_sync(0xffffffffu, v0, off);
                v1 += __shfl_xor_sync(0xffffffffu, v1, off);
                v2 += __shfl_xor_sync(0xffffffffu, v2, off);
                v3 += __shfl_xor_sync(0xffffffffu, v3, off);
            }
            if (l < 8)
                *(float4*)&ps_s[half * 1024 + (rbase + rr) * 32 + cq * 4] =
                    make_float4(v0, v1, v2, v3);
        }
    }
    __syncthreads();

    // ---- combine halves + scale + bias + store: warp w rows 2w, 2w+1 ----
    {
        const float bv = bias[h * Cc + l];
        #pragma unroll
        for (int rs = 0; rs < 2; rs++) {
            const int r = 2 * w + rs;
            float val = ps_s[r * 32 + l] + ps_s[1024 + r * 32 + l];
            out[(b * Nn + i0 + r) * ODIM + h * Cc + l] = val * rinv_s[r] + bv;
        }
    }
}

// ---------------------------------------------------------------------------
extern "C" void kernel_launch(void* const* d_in, const int* in_sizes, int n_in,
                              void* d_out, int out_size)
{
    const float* x    = (const float*)d_in[0];
    const int*   adj  = (const int*)  d_in[1];
    const float* Wl   = (const float*)d_in[2];
    const float* bl   = (const float*)d_in[3];
    const float* Wr   = (const float*)d_in[4];
    const float* br   = (const float*)d_in[5];
    const float* att  = (const float*)d_in[6];
    const float* bias = (const float*)d_in[7];
    float* out = (float*)d_out;

    cudaFuncSetAttribute(gat_kernel, cudaFuncAttributeMaxDynamicSharedMemorySize, SMEM_BYTES);

    dim3 g0(Bn, 16, 8);
    mask_kernel<<<g0, 256>>>(adj);

    dim3 g1(Bn * Nn / BM, (2 * ODIM) / BN);   // (64, 4)
    proj_kernel<<<g1, 256>>>(x, Wl, bl, Wr, br);

    dim3 g2(Nn / 32, Hh, Bn);                 // (16, 4, 8)
    gat_kernel<<<g2, 512, SMEM_BYTES>>>(att, bias, out);
}

// round 6
// speedup vs baseline: 3.3084x; 1.0432x over previous
#include <cuda_runtime.h>

// ---------------------------------------------------------------------------
// BatchedGAT: B=8, N=512, IN=256, H=4, C=32, OUT=128, LeakyReLU slope 0.2
// K0: mask precompute (head-invariant): bit-packed adjacency^T + forced diag
// K1: projections xl = x@W_l + b_l, xr = x@W_r + b_r  -> [B,H,N,C]
// K2: e_ij = v_j + sum_c 0.4*att_c*|xr_ic + xl_jc|  (linear xr part cancels
//     in softmax; xl part = v_j), masked softmax, out = (p@xl)/rowsum + bias
// ---------------------------------------------------------------------------

#define Bn 8
#define Nn 512
#define INDIM 256
#define Hh 4
#define Cc 32
#define ODIM 128

typedef unsigned long long u64;

__device__ float g_xl[Bn * Hh * Nn * Cc];        // [b][h][j][c]
__device__ float g_xr[Bn * Hh * Nn * Cc];        // [b][h][i][c]
__device__ unsigned g_mask[Bn * 16 * Nn];        // [b][iw][j], bit i(local)

__device__ __forceinline__ u64 f2add(u64 a, u64 b) {
    u64 r; asm("add.rn.f32x2 %0, %1, %2;" : "=l"(r) : "l"(a), "l"(b)); return r;
}
__device__ __forceinline__ u64 f2fma(u64 a, u64 b, u64 c) {
    u64 r; asm("fma.rn.f32x2 %0, %1, %2, %3;" : "=l"(r) : "l"(a), "l"(b), "l"(c)); return r;
}
__device__ __forceinline__ float2 f2unpack(u64 v) {
    float2 r; asm("mov.b64 {%0, %1}, %2;" : "=f"(r.x), "=f"(r.y) : "l"(v)); return r;
}

#define ABSMASK 0x7FFFFFFF7FFFFFFFULL
#define NEGINF  __int_as_float(0xff800000)

// ---------------------------------------------------------------------------
// Kernel 0: mask precompute. grid (8, 16, 4), block 256; warp owns 16 j's.
// ---------------------------------------------------------------------------
__global__ void __launch_bounds__(256) mask_kernel(const int* __restrict__ adj)
{
    const int b = blockIdx.x, iw = blockIdx.y, jc = blockIdx.z;
    const int w = threadIdx.x >> 5, l = threadIdx.x & 31;
    const int ig = iw * 32 + l;
    const int* a = adj + b * Nn * Nn + iw * 32 + l;
    unsigned* dst = g_mask + (b * 16 + iw) * Nn;
    const int j0 = jc * 128 + w * 16;

    int av[16];
    #pragma unroll
    for (int k = 0; k < 16; k++) av[k] = a[(j0 + k) * Nn];   // MLP 16
    #pragma unroll
    for (int k = 0; k < 16; k++) {
        const int j = j0 + k;
        unsigned word = __ballot_sync(0xffffffffu, (av[k] != 0) || (j == ig));
        if (l == 0) dst[j] = word;
    }
}

// ---------------------------------------------------------------------------
// Kernel 1: tiled SIMT GEMM (scalar FFMA). M=4096, K=256, Ncols=256 (xl | xr)
// ---------------------------------------------------------------------------
#define BM 64
#define BN 64
#define BK 16

__global__ void __launch_bounds__(256) proj_kernel(
    const float* __restrict__ x,
    const float* __restrict__ Wl, const float* __restrict__ bl,
    const float* __restrict__ Wr, const float* __restrict__ br)
{
    __shared__ float As[BK][BM + 4];
    __shared__ float Bs[BK][BN + 4];

    const int tid = threadIdx.x;
    const int m0 = blockIdx.x * BM;
    const int n0 = blockIdx.y * BN;
    const float* W  = (n0 < 128) ? Wl : Wr;
    const float* bb = (n0 < 128) ? bl : br;
    const int wcol0 = n0 & 127;

    const int ty = tid >> 4;
    const int tx = tid & 15;
    const int ar  = tid >> 2;
    const int ak4 = (tid & 3) << 2;
    const int bk  = tid >> 4;
    const int bn4 = (tid & 15) << 2;

    float acc[4][4];
    #pragma unroll
    for (int r = 0; r < 4; r++)
        #pragma unroll
        for (int c = 0; c < 4; c++) acc[r][c] = 0.f;

    for (int k0 = 0; k0 < INDIM; k0 += BK) {
        float4 av = *(const float4*)&x[(m0 + ar) * INDIM + k0 + ak4];
        As[ak4 + 0][ar] = av.x;
        As[ak4 + 1][ar] = av.y;
        As[ak4 + 2][ar] = av.z;
        As[ak4 + 3][ar] = av.w;
        float4 bv = *(const float4*)&W[(k0 + bk) * ODIM + wcol0 + bn4];
        *(float4*)&Bs[bk][bn4] = bv;
        __syncthreads();

        #pragma unroll
        for (int kk = 0; kk < BK; kk++) {
            float4 a = *(const float4*)&As[kk][ty * 4];
            float4 b = *(const float4*)&Bs[kk][tx * 4];
            float aa[4] = {a.x, a.y, a.z, a.w};
            float bbv[4] = {b.x, b.y, b.z, b.w};
            #pragma unroll
            for (int r = 0; r < 4; r++)
                #pragma unroll
                for (int c = 0; c < 4; c++) acc[r][c] += aa[r] * bbv[c];
        }
        __syncthreads();
    }

    #pragma unroll
    for (int r = 0; r < 4; r++) {
        const int m = m0 + ty * 4 + r;
        const int bidx = m >> 9;
        const int n = m & 511;
        #pragma unroll
        for (int c = 0; c < 4; c++) {
            const int oc = n0 + tx * 4 + c;
            float v = acc[r][c] + bb[wcol0 + tx * 4 + c];
            const int h = (oc & 127) >> 5;
            const int ch = oc & 31;
            float* dst = (oc < 128) ? g_xl : g_xr;
            dst[(((bidx * Hh + h) * Nn) + n) * Cc + ch] = v;
        }
    }
}

// ---------------------------------------------------------------------------
// Kernel 2: attention. grid (16, 4, 8), 512 threads.
// ---------------------------------------------------------------------------
#define XL_ST 36
#define ES_ST 516
#define SM_XL   0                          // 512*36 = 18432
#define SM_XR   (SM_XL + Nn * XL_ST)       // 1024
#define SM_ES   (SM_XR + 1024)             // 32*516 = 16512
#define SM_MASK (SM_ES + 32 * ES_ST)       // 512
#define SM_W4   (SM_MASK + 512)            // 32
#define SM_W6   (SM_W4 + 32)               // 32
#define SM_RINV (SM_W6 + 32)               // 32
#define SM_PS   (SM_RINV + 32)             // 2 halves * 32 rows * 32 ch = 2048
#define SM_FLOATS (SM_PS + 2048)
#define SMEM_BYTES (SM_FLOATS * 4)         // ~154.5 KB

__global__ void __launch_bounds__(512) gat_kernel(
    const float* __restrict__ att,
    const float* __restrict__ bias,
    float* __restrict__ out)
{
    extern __shared__ float sm[];
    float* xl_s = sm + SM_XL;
    float* xr_s = sm + SM_XR;
    float* e_s  = sm + SM_ES;
    unsigned* mask_s = (unsigned*)(sm + SM_MASK);
    float* w4_s = sm + SM_W4;
    float* w6_s = sm + SM_W6;
    float* rinv_s = sm + SM_RINV;
    float* ps_s = sm + SM_PS;

    const int tid = threadIdx.x;
    const int w = tid >> 5;
    const int l = tid & 31;
    const int b  = blockIdx.z;
    const int h  = blockIdx.y;
    const int bx = blockIdx.x;
    const int i0 = bx * 32;

    const float* xl = g_xl + ((b * Hh + h) * Nn) * Cc;
    const float* xr = g_xr + ((b * Hh + h) * Nn + i0) * Cc;

    // ---- loads ----
    #pragma unroll
    for (int q8 = 0; q8 < 8; q8++) {
        int idx = q8 * 512 + tid;          // 4096 float4
        int j = idx >> 3, cc = (idx & 7) << 2;
        *(float4*)&xl_s[j * XL_ST + cc] = *(const float4*)&xl[j * Cc + cc];
    }
    if (tid < 256) {
        int j = tid >> 3, cc = (tid & 7) << 2;
        *(float4*)&xr_s[j * Cc + cc] = *(const float4*)&xr[j * Cc + cc];
    }
    mask_s[tid] = g_mask[(b * 16 + bx) * Nn + tid];
    if (tid < 32) {
        float a = att[h * Cc + tid];
        w4_s[tid] = 0.4f * a;
        w6_s[tid] = 0.6f * a;
    }
    __syncthreads();

    // ---- Phase 1: e scores, j-sliced. Warp w owns j = 32w + l ----
    {
        const int j = w * 32 + l;
        u64 q[16];
        {
            const ulonglong2* qp = (const ulonglong2*)&xl_s[j * XL_ST];
            #pragma unroll
            for (int k = 0; k < 8; k++) { ulonglong2 t = qp[k]; q[2*k] = t.x; q[2*k+1] = t.y; }
        }
        u64 w4r[16];
        {
            const ulonglong2* wp = (const ulonglong2*)w4_s;
            #pragma unroll
            for (int k = 0; k < 8; k++) { ulonglong2 t = wp[k]; w4r[2*k] = t.x; w4r[2*k+1] = t.y; }
        }
        float v;
        {
            const u64* w6p = (const u64*)w6_s;
            u64 va = 0ull, vb = 0ull;
            #pragma unroll
            for (int k = 0; k < 16; k += 2) {
                va = f2fma(w6p[k],   q[k],   va);
                vb = f2fma(w6p[k+1], q[k+1], vb);
            }
            float2 f = f2unpack(f2add(va, vb));
            v = f.x + f.y;
        }
        const unsigned m = mask_s[j];
        float* erow = &e_s[w * 32 + l];

        #pragma unroll 4
        for (int i = 0; i < 32; i++) {
            const ulonglong2* xp = (const ulonglong2*)&xr_s[i * Cc];
            u64 a0 = 0ull, a1 = 0ull, a2 = 0ull, a3 = 0ull;
            #pragma unroll
            for (int k = 0; k < 8; k += 2) {
                ulonglong2 t0 = xp[k], t1 = xp[k+1];
                u64 s0 = f2add(t0.x, q[2*k])   & ABSMASK;
                u64 s1 = f2add(t0.y, q[2*k+1]) & ABSMASK;
                u64 s2 = f2add(t1.x, q[2*k+2]) & ABSMASK;
                u64 s3 = f2add(t1.y, q[2*k+3]) & ABSMASK;
                a0 = f2fma(w4r[2*k],   s0, a0);
                a1 = f2fma(w4r[2*k+1], s1, a1);
                a2 = f2fma(w4r[2*k+2], s2, a2);
                a3 = f2fma(w4r[2*k+3], s3, a3);
            }
            float2 f = f2unpack(f2add(f2add(a0, a1), f2add(a2, a3)));
            float e = f.x + f.y + v;
            e = ((m >> i) & 1u) ? e : NEGINF;
            erow[i * ES_ST] = e;
        }
    }
    __syncthreads();

    // ---- Phase 2: masked softmax. Warp w owns rows 2w, 2w+1 ----
    #pragma unroll
    for (int rs = 0; rs < 2; rs++) {
        const int r = 2 * w + rs;
        float vals[16];
        #pragma unroll
        for (int p4 = 0; p4 < 4; p4++) {
            float4 f = *(float4*)&e_s[r * ES_ST + p4 * 128 + l * 4];
            vals[p4*4]   = f.x; vals[p4*4+1] = f.y;
            vals[p4*4+2] = f.z; vals[p4*4+3] = f.w;
        }
        float mx = vals[0];
        #pragma unroll
        for (int k = 1; k < 16; k++) mx = fmaxf(mx, vals[k]);
        #pragma unroll
        for (int off = 16; off > 0; off >>= 1)
            mx = fmaxf(mx, __shfl_xor_sync(0xffffffffu, mx, off));
        float sum = 0.f;
        #pragma unroll
        for (int k = 0; k < 16; k++) {
            float p = __expf(vals[k] - mx);
            vals[k] = p;
            sum += p;
        }
        #pragma unroll
        for (int off = 16; off > 0; off >>= 1)
            sum += __shfl_xor_sync(0xffffffffu, sum, off);
        #pragma unroll
        for (int p4 = 0; p4 < 4; p4++) {
            *(float4*)&e_s[r * ES_ST + p4 * 128 + l * 4] =
                make_float4(vals[p4*4], vals[p4*4+1], vals[p4*4+2], vals[p4*4+3]);
        }
        if (l == 0) rinv_s[r] = 1.f / sum;
    }
    __syncthreads();

    // ---- Phase D (scalar): warp w -> rows 4*(w&7)..+3, j-half (w>>3)*256 ----
    {
        const int rbase = 4 * (w & 7);
        const int half = w >> 3;
        const int J0 = half * 256;
        const int jp = l >> 3, cq = l & 7;
        float acc[4][4];
        #pragma unroll
        for (int rr = 0; rr < 4; rr++)
            #pragma unroll
            for (int k = 0; k < 4; k++) acc[rr][k] = 0.f;

        #pragma unroll 2
        for (int jjc = 0; jjc < 8; jjc++) {
            const int jbase = J0 + jjc * 32 + jp;
            #pragma unroll
            for (int g = 0; g < 8; g++) {
                const int jrow = jbase + g * 4;
                float4 xv = *(const float4*)&xl_s[jrow * XL_ST + cq * 4];
                #pragma unroll
                for (int rr = 0; rr < 4; rr++) {
                    float p = e_s[(rbase + rr) * ES_ST + jrow];
                    acc[rr][0] += p * xv.x;
                    acc[rr][1] += p * xv.y;
                    acc[rr][2] += p * xv.z;
                    acc[rr][3] += p * xv.w;
                }
            }
        }
        // reduce over jp (lane bits 3,4)
        #pragma unroll
        for (int off = 8; off <= 16; off <<= 1)
            #pragma unroll
            for (int rr = 0; rr < 4; rr++)
                #pragma unroll
                for (int k = 0; k < 4; k++)
                    acc[rr][k] += __shfl_xor_sync(0xffffffffu, acc[rr][k], off);

        if (l < 8) {
            #pragma unroll
            for (int rr = 0; rr < 4; rr++)
                *(float4*)&ps_s[half * 1024 + (rbase + rr) * 32 + cq * 4] =
                    make_float4(acc[rr][0], acc[rr][1], acc[rr][2], acc[rr][3]);
        }
    }
    __syncthreads();

    // ---- combine halves + scale + bias + store: warp w rows 2w, 2w+1 ----
    {
        const float bv = bias[h * Cc + l];
        #pragma unroll
        for (int rs = 0; rs < 2; rs++) {
            const int r = 2 * w + rs;
            float val = ps_s[r * 32 + l] + ps_s[1024 + r * 32 + l];
            out[(b * Nn + i0 + r) * ODIM + h * Cc + l] = val * rinv_s[r] + bv;
        }
    }
}

// ---------------------------------------------------------------------------
extern "C" void kernel_launch(void* const* d_in, const int* in_sizes, int n_in,
                              void* d_out, int out_size)
{
    const float* x    = (const float*)d_in[0];
    const int*   adj  = (const int*)  d_in[1];
    const float* Wl   = (const float*)d_in[2];
    const float* bl   = (const float*)d_in[3];
    const float* Wr   = (const float*)d_in[4];
    const float* br   = (const float*)d_in[5];
    const float* att  = (const float*)d_in[6];
    const float* bias = (const float*)d_in[7];
    float* out = (float*)d_out;

    cudaFuncSetAttribute(gat_kernel, cudaFuncAttributeMaxDynamicSharedMemorySize, SMEM_BYTES);

    dim3 g0(Bn, 16, 4);
    mask_kernel<<<g0, 256>>>(adj);

    dim3 g1(Bn * Nn / BM, (2 * ODIM) / BN);   // (64, 4)
    proj_kernel<<<g1, 256>>>(x, Wl, bl, Wr, br);

    dim3 g2(Nn / 32, Hh, Bn);                 // (16, 4, 8)
    gat_kernel<<<g2, 512, SMEM_BYTES>>>(att, bias, out);
}